// round 2
// baseline (speedup 1.0000x reference)
#include <cuda_runtime.h>
#include <math_constants.h>

#define NQ 1024
#define NK 2048
#define D  64

// Scratch (no allocs allowed in kernel_launch)
__device__ float g_qp [NQ * D];   // qp[q][h]
__device__ float g_kpb[NK * D];   // kp[k][h] + b1[h]
__device__ float g_vt [NK * D];   // value transposed: vt[k][d]
__device__ float g_rmax[NQ];
__device__ float g_rinv[NQ];      // 1 / sum(exp(s - max))

// ---------------------------------------------------------------------------
// Kernel 1: projections.  blocks [0,NQ) -> qp column q ; [NQ,NQ+NK) -> kpb col k
// 64 threads per block, thread t = output feature h.
// ---------------------------------------------------------------------------
__global__ void k_proj(const float* __restrict__ query,
                       const float* __restrict__ key,
                       const float* __restrict__ W1,
                       const float* __restrict__ b1)
{
    __shared__ float col[D];
    __shared__ float Ws[D][D + 1];

    int b = blockIdx.x;
    int t = threadIdx.x;                 // h
    bool isQ = (b < NQ);
    int c = isQ ? b : (b - NQ);
    const float* src = isQ ? query : key;
    int stride = isQ ? NQ : NK;
    int wofs = isQ ? 0 : D;

    col[t] = src[t * stride + c];
    for (int i = t; i < D * D; i += 64) {
        int h = i >> 6, d = i & 63;
        Ws[h][d] = W1[h * (2 * D) + wofs + d];
    }
    __syncthreads();

    float acc = isQ ? 0.0f : b1[t];
    #pragma unroll 16
    for (int d = 0; d < D; d++) acc += Ws[t][d] * col[d];

    float* dst = isQ ? (g_qp + c * D) : (g_kpb + c * D);
    dst[t] = acc;
}

// ---------------------------------------------------------------------------
// Kernel 1b: transpose value [d][k] -> vt[k][d]
// ---------------------------------------------------------------------------
__global__ void k_transpose(const float* __restrict__ value)
{
    int idx = blockIdx.x * blockDim.x + threadIdx.x;   // over NK*D
    if (idx >= NK * D) return;
    int k = idx >> 6, d = idx & 63;
    g_vt[idx] = value[d * NK + k];
}

// ---------------------------------------------------------------------------
// Kernel 2: scores[q][k] = sum_h W2[h]*relu(qp[q][h]+kpb[k][h]) + b2
// Block: 64q x 64k tile, 256 threads, each thread 4x4.
// ---------------------------------------------------------------------------
__global__ void k_scores(const float* __restrict__ W2,
                         const float* __restrict__ b2,
                         float* __restrict__ scores)
{
    __shared__ float qs[64][65];
    __shared__ float ks[64][65];
    __shared__ float w2s[64];

    int qbase = blockIdx.x * 64;
    int kbase = blockIdx.y * 64;
    int tid = threadIdx.x;

    for (int i = tid; i < 64 * 64; i += 256) {
        int r = i >> 6, c = i & 63;
        qs[r][c] = g_qp [(qbase + r) * D + c];
        ks[r][c] = g_kpb[(kbase + r) * D + c];
    }
    if (tid < 64) w2s[tid] = W2[tid];
    __syncthreads();

    int tx = tid & 15;       // k sub-index
    int ty = tid >> 4;       // q sub-index

    float acc[4][4];
    #pragma unroll
    for (int i = 0; i < 4; i++)
        #pragma unroll
        for (int j = 0; j < 4; j++) acc[i][j] = 0.0f;

    #pragma unroll 8
    for (int h = 0; h < 64; h++) {
        float w = w2s[h];
        float a[4], bb[4];
        #pragma unroll
        for (int i = 0; i < 4; i++) a[i] = qs[ty + 16 * i][h];
        #pragma unroll
        for (int j = 0; j < 4; j++) bb[j] = ks[tx + 16 * j][h];
        #pragma unroll
        for (int i = 0; i < 4; i++)
            #pragma unroll
            for (int j = 0; j < 4; j++)
                acc[i][j] += w * fmaxf(a[i] + bb[j], 0.0f);
    }

    float bias = b2[0];
    #pragma unroll
    for (int i = 0; i < 4; i++) {
        int q = qbase + ty + 16 * i;
        #pragma unroll
        for (int j = 0; j < 4; j++) {
            int k = kbase + tx + 16 * j;
            scores[q * NK + k] = acc[i][j] + bias;
        }
    }
}

// ---------------------------------------------------------------------------
// Kernel 3: per-row softmax stats (max, 1/sum). One block per q row.
// ---------------------------------------------------------------------------
__global__ void k_stats(const float* __restrict__ scores)
{
    __shared__ float red[256];
    int q = blockIdx.x;
    int t = threadIdx.x;
    const float* row = scores + q * NK;

    float m = -CUDART_INF_F;
    for (int k = t; k < NK; k += 256) m = fmaxf(m, row[k]);
    red[t] = m;
    __syncthreads();
    for (int s = 128; s > 0; s >>= 1) {
        if (t < s) red[t] = fmaxf(red[t], red[t + s]);
        __syncthreads();
    }
    m = red[0];
    __syncthreads();

    float sum = 0.0f;
    for (int k = t; k < NK; k += 256) sum += __expf(row[k] - m);
    red[t] = sum;
    __syncthreads();
    for (int s = 128; s > 0; s >>= 1) {
        if (t < s) red[t] += red[t + s];
        __syncthreads();
    }
    if (t == 0) {
        g_rmax[q] = m;
        g_rinv[q] = 1.0f / red[0];
    }
}

// ---------------------------------------------------------------------------
// Kernel 4: out[d][q] = sum_k p[q][k] * vt[k][d],  p = exp(s-m)*invZ on the fly.
// Block: 8 q's, 256 threads = 8 warps, warp w owns q = qbase + w.
// K-tiles of 128; value tile in smem, p tile in smem.
// ---------------------------------------------------------------------------
__global__ void k_pv(const float* __restrict__ scores,
                     float* __restrict__ out)
{
    __shared__ float vs[128][64];       // vs[kk][d]
    __shared__ float ps[128][9];        // ps[kk][qq], pad 9 (gcd(9,32)=1)

    int qbase = blockIdx.x * 8;
    int tid = threadIdx.x;
    int w = tid >> 5, lane = tid & 31;
    int q = qbase + w;

    float m = g_rmax[q];
    float invz = g_rinv[q];

    float acc0 = 0.0f, acc1 = 0.0f;     // d = 2*lane, 2*lane+1

    for (int kt = 0; kt < NK; kt += 128) {
        __syncthreads();
        // load V tile: 128 x 64 floats via float4 (2048 float4 / 256 thr = 8 ea)
        for (int i = tid; i < (128 * 64) / 4; i += 256) {
            int e = 4 * i;
            int kk = e >> 6, d = e & 63;
            *(float4*)&vs[kk][d] = *(const float4*)&g_vt[(kt + kk) * D + d];
        }
        // p tile: 8 q rows x 128 k, coalesced reads of scores
        for (int i = tid; i < 8 * 128; i += 256) {
            int qq = i >> 7, kk = i & 127;
            int qg = qbase + qq;
            ps[kk][qq] = __expf(scores[qg * NK + kt + kk] - g_rmax[qg]) * g_rinv[qg];
        }
        __syncthreads();

        #pragma unroll 8
        for (int kk = 0; kk < 128; kk++) {
            float p = ps[kk][w];
            float2 v = *(float2*)&vs[kk][2 * lane];
            acc0 += p * v.x;
            acc1 += p * v.y;
        }
    }

    // out layout: [d][q], d-major
    out[(2 * lane    ) * NQ + q] = acc0;
    out[(2 * lane + 1) * NQ + q] = acc1;
    (void)m; (void)invz;
}

// ---------------------------------------------------------------------------
extern "C" void kernel_launch(void* const* d_in, const int* in_sizes, int n_in,
                              void* d_out, int out_size)
{
    const float* query = (const float*)d_in[0];   // [64,1024]
    const float* key   = (const float*)d_in[1];   // [64,2048]
    const float* value = (const float*)d_in[2];   // [64,2048]
    const float* W1    = (const float*)d_in[3];   // [64,128]
    const float* b1    = (const float*)d_in[4];   // [64]
    const float* W2    = (const float*)d_in[5];   // [1,64]
    const float* b2    = (const float*)d_in[6];   // [1]

    float* out_p    = (float*)d_out;                  // [64,1024]
    float* scores_p = (float*)d_out + NQ * D;         // [1024,2048]

    k_proj<<<NQ + NK, 64>>>(query, key, W1, b1);
    k_transpose<<<(NK * D + 255) / 256, 256>>>(value);

    dim3 gs(NQ / 64, NK / 64);
    k_scores<<<gs, 256>>>(W2, b2, scores_p);

    k_stats<<<NQ, 256>>>(scores_p);

    k_pv<<<NQ / 8, 256>>>(scores_p, out_p);
}

// round 3
// speedup vs baseline: 1.8732x; 1.8732x over previous
#include <cuda_runtime.h>
#include <math_constants.h>

#define NQ 1024
#define NK 2048
#define D  64
typedef unsigned long long ull;

__device__ float g_qp [NQ * D];
__device__ float g_kpb[NK * D];
__device__ float g_vt [NK * D];
__device__ float g_rmax[NQ];
__device__ float g_rinv[NQ];

__device__ __forceinline__ unsigned su32(const void* p) {
    return (unsigned)__cvta_generic_to_shared(p);
}
#define CPA16(dst, src) asm volatile("cp.async.ca.shared.global [%0], [%1], 16;" :: "r"(dst), "l"(src))
#define CPCOMMIT() asm volatile("cp.async.commit_group;")
#define CPWAIT() asm volatile("cp.async.wait_group 0;")
#define FMA2(acc, a, b) asm("fma.rn.f32x2 %0, %1, %2, %0;" : "+l"(acc) : "l"(a), "l"(b))
#define RELU_FMA2(acc, a, b, w) asm("{\n\t.reg .b64 t;\n\t.reg .f32 lo, hi;\n\t" \
    "add.rn.f32x2 t, %1, %2;\n\tmov.b64 {lo, hi}, t;\n\t"                        \
    "max.f32 lo, lo, 0f00000000;\n\tmax.f32 hi, hi, 0f00000000;\n\t"             \
    "mov.b64 t, {lo, hi};\n\tfma.rn.f32x2 %0, %3, t, %0;\n\t}"                   \
    : "+l"(acc) : "l"(a), "l"(b), "l"(w))

// ---- Kernel 1: projections. 48 blocks x 256 thr, 64 columns per block. ----
__global__ void __launch_bounds__(256) k_proj(const float* __restrict__ query,
                                              const float* __restrict__ key,
                                              const float* __restrict__ W1,
                                              const float* __restrict__ b1)
{
    __shared__ float Ws[D][D];
    __shared__ float Xs[D][64];
    int b = blockIdx.x;
    bool isQ = (b < 16);
    int c0 = (isQ ? b : (b - 16)) * 64;
    const float* src = isQ ? query : key;
    int stride = isQ ? NQ : NK;
    int wofs = isQ ? 0 : D;
    int tid = threadIdx.x;

    {
        int h = tid >> 2, ds = (tid & 3) * 16;
        const float* wr = W1 + h * (2 * D) + wofs + ds;
        #pragma unroll
        for (int j = 0; j < 4; j++) {
            float4 v = *(const float4*)(wr + 4 * j);
            Ws[ds + 4*j + 0][h] = v.x; Ws[ds + 4*j + 1][h] = v.y;
            Ws[ds + 4*j + 2][h] = v.z; Ws[ds + 4*j + 3][h] = v.w;
        }
    }
    {
        int d = tid >> 2, cs = (tid & 3) * 16;
        #pragma unroll
        for (int j = 0; j < 4; j++)
            *(float4*)&Xs[d][cs + 4*j] = *(const float4*)&src[d * stride + c0 + cs + 4*j];
    }
    __syncthreads();

    int h = tid & 63, cg = tid >> 6;
    float acc[16];
    float bias = isQ ? 0.0f : b1[h];
    #pragma unroll
    for (int j = 0; j < 16; j++) acc[j] = bias;

    #pragma unroll 8
    for (int d = 0; d < D; d++) {
        float w = Ws[d][h];
        #pragma unroll
        for (int j = 0; j < 16; j++) acc[j] += w * Xs[d][cg * 16 + j];
    }
    float* dst = isQ ? g_qp : g_kpb;
    #pragma unroll
    for (int j = 0; j < 16; j++)
        dst[(c0 + cg * 16 + j) * D + h] = acc[j];
}

// ---- Kernel 1b: coalesced transpose value[d][k] -> g_vt[k][d] ----
__global__ void k_transpose(const float* __restrict__ value)
{
    __shared__ float tile[32][33];
    int kx = blockIdx.x * 32 + threadIdx.x;
    int d0 = blockIdx.y * 32;
    #pragma unroll
    for (int j = 0; j < 32; j += 8)
        tile[threadIdx.y + j][threadIdx.x] = value[(d0 + threadIdx.y + j) * NK + kx];
    __syncthreads();
    int dx = d0 + threadIdx.x;
    int k0 = blockIdx.x * 32;
    #pragma unroll
    for (int j = 0; j < 32; j += 8)
        g_vt[(k0 + threadIdx.y + j) * D + dx] = tile[threadIdx.x][threadIdx.y + j];
}

// ---- Kernel 2: scores = W2·relu(qp+kpb) + b2, 64x64 tile, f32x2 packed ----
__global__ void __launch_bounds__(256) k_scores(const float* __restrict__ W2,
                                                const float* __restrict__ b2,
                                                float* __restrict__ scores)
{
    __shared__ float qs[64][66];
    __shared__ float ks[64][66];
    __shared__ ull w2s[32];
    int qbase = blockIdx.x * 64, kbase = blockIdx.y * 64;
    int tid = threadIdx.x;

    for (int i = tid; i < 64 * 32; i += 256) {
        int r = i >> 5, c = (i & 31) * 2;
        *(float2*)&qs[r][c] = *(const float2*)&g_qp [(qbase + r) * D + c];
        *(float2*)&ks[r][c] = *(const float2*)&g_kpb[(kbase + r) * D + c];
    }
    if (tid < 32) {
        float2 w = *(const float2*)&W2[2 * tid];
        ull p; asm("mov.b64 %0, {%1,%2};" : "=l"(p) : "f"(w.x), "f"(w.y));
        w2s[tid] = p;
    }
    __syncthreads();

    int tx = tid & 15, ty = tid >> 4;
    ull acc[4][4];
    #pragma unroll
    for (int i = 0; i < 4; i++)
        #pragma unroll
        for (int j = 0; j < 4; j++) acc[i][j] = 0ull;

    #pragma unroll 4
    for (int h = 0; h < 64; h += 2) {
        ull w2 = w2s[h >> 1];
        ull a[4], bb[4];
        #pragma unroll
        for (int i = 0; i < 4; i++) a[i]  = *(ull*)&qs[ty + 16 * i][h];
        #pragma unroll
        for (int j = 0; j < 4; j++) bb[j] = *(ull*)&ks[tx + 16 * j][h];
        #pragma unroll
        for (int i = 0; i < 4; i++)
            #pragma unroll
            for (int j = 0; j < 4; j++)
                RELU_FMA2(acc[i][j], a[i], bb[j], w2);
    }

    float bias = b2[0];
    #pragma unroll
    for (int i = 0; i < 4; i++) {
        int q = qbase + ty + 16 * i;
        #pragma unroll
        for (int j = 0; j < 4; j++) {
            float lo, hi;
            asm("mov.b64 {%0,%1}, %2;" : "=f"(lo), "=f"(hi) : "l"(acc[i][j]));
            scores[q * NK + kbase + tx + 16 * j] = lo + hi + bias;
        }
    }
}

// ---- Kernel 3: softmax stats, single pass in registers ----
__global__ void __launch_bounds__(256) k_stats(const float* __restrict__ scores)
{
    __shared__ float red[8];
    int q = blockIdx.x, t = threadIdx.x;
    const float4* row = (const float4*)(scores + q * NK);
    float4 a = row[t], b = row[t + 256];

    float m = fmaxf(fmaxf(fmaxf(a.x, a.y), fmaxf(a.z, a.w)),
                    fmaxf(fmaxf(b.x, b.y), fmaxf(b.z, b.w)));
    #pragma unroll
    for (int o = 16; o > 0; o >>= 1) m = fmaxf(m, __shfl_xor_sync(~0u, m, o));
    if ((t & 31) == 0) red[t >> 5] = m;
    __syncthreads();
    float bm = red[0];
    #pragma unroll
    for (int i = 1; i < 8; i++) bm = fmaxf(bm, red[i]);
    __syncthreads();

    float s = __expf(a.x - bm) + __expf(a.y - bm) + __expf(a.z - bm) + __expf(a.w - bm)
            + __expf(b.x - bm) + __expf(b.y - bm) + __expf(b.z - bm) + __expf(b.w - bm);
    #pragma unroll
    for (int o = 16; o > 0; o >>= 1) s += __shfl_xor_sync(~0u, s, o);
    if ((t & 31) == 0) red[t >> 5] = s;
    __syncthreads();
    if (t == 0) {
        float tot = 0.0f;
        #pragma unroll
        for (int i = 0; i < 8; i++) tot += red[i];
        g_rmax[q] = bm;
        g_rinv[q] = 1.0f / tot;
    }
}

// ---- Kernel 4: out[d][q] = sum_k p*vt. 128 blocks x 8q, warps split kk. ----
__global__ void __launch_bounds__(256) k_pv(const float* __restrict__ scores,
                                            float* __restrict__ out)
{
    __shared__ float vs[2][64][68];   // 34.8 KB, row stride 272B (16B aligned)
    __shared__ float ps[2][64][8];

    int q0 = blockIdx.x * 8;
    int tid = threadIdx.x, w = tid >> 5, lane = tid & 31;

    int sq = tid & 7, skk = tid >> 3;          // p staging: (q0+sq, kk=skk|skk+32)
    float rm = g_rmax[q0 + sq], ri = g_rinv[q0 + sq];
    const float* srow = scores + (q0 + sq) * NK + skk;

    int vk = tid >> 2, vh = (tid & 3) * 16;    // v staging: row vk, 16 floats

    {
        const float* src = g_vt + vk * D + vh;
        unsigned dst = su32(&vs[0][vk][vh]);
        #pragma unroll
        for (int j = 0; j < 4; j++) CPA16(dst + 16 * j, src + 4 * j);
        CPCOMMIT();
    }
    float sc0 = srow[0], sc1 = srow[32];

    ull accx[4] = {0,0,0,0};   // d = 2*lane,   q pairs (0,1)(2,3)(4,5)(6,7)
    ull accy[4] = {0,0,0,0};   // d = 2*lane+1

    for (int t = 0; t < 32; t++) {
        int buf = t & 1;
        CPWAIT();
        __syncthreads();
        ps[buf][skk     ][sq] = __expf(sc0 - rm) * ri;
        ps[buf][skk + 32][sq] = __expf(sc1 - rm) * ri;
        if (t < 31) {
            const float* src = g_vt + ((t + 1) * 64 + vk) * D + vh;
            unsigned dst = su32(&vs[buf ^ 1][vk][vh]);
            #pragma unroll
            for (int j = 0; j < 4; j++) CPA16(dst + 16 * j, src + 4 * j);
            CPCOMMIT();
            sc0 = srow[(t + 1) * 64];
            sc1 = srow[(t + 1) * 64 + 32];
        }
        __syncthreads();

        int kb = w * 8;
        #pragma unroll
        for (int u = 0; u < 8; u++) {
            int kk = kb + u;
            float2 v = *(float2*)&vs[buf][kk][2 * lane];
            ulonglong2 pA = *(ulonglong2*)&ps[buf][kk][0];
            ulonglong2 pB = *(ulonglong2*)&ps[buf][kk][4];
            ull vx, vy;
            asm("mov.b64 %0, {%1,%1};" : "=l"(vx) : "f"(v.x));
            asm("mov.b64 %0, {%1,%1};" : "=l"(vy) : "f"(v.y));
            FMA2(accx[0], pA.x, vx); FMA2(accx[1], pA.y, vx);
            FMA2(accx[2], pB.x, vx); FMA2(accx[3], pB.y, vx);
            FMA2(accy[0], pA.x, vy); FMA2(accy[1], pA.y, vy);
            FMA2(accy[2], pB.x, vy); FMA2(accy[3], pB.y, vy);
        }
    }

    // cross-warp reduction: red[w][lane][j], j<8: d=2lane q=j; j>=8: d=2lane+1
    __syncthreads();
    float* red = (float*)vs;
    int base = (w * 32 + lane) * 16;
    #pragma unroll
    for (int jp = 0; jp < 4; jp++) {
        float lo, hi;
        asm("mov.b64 {%0,%1}, %2;" : "=f"(lo), "=f"(hi) : "l"(accx[jp]));
        red[base + 2 * jp] = lo; red[base + 2 * jp + 1] = hi;
        asm("mov.b64 {%0,%1}, %2;" : "=f"(lo), "=f"(hi) : "l"(accy[jp]));
        red[base + 8 + 2 * jp] = lo; red[base + 8 + 2 * jp + 1] = hi;
    }
    __syncthreads();

    #pragma unroll
    for (int r = tid; r < 512; r += 256) {
        int d = r >> 3, q = r & 7;
        int ln = d >> 1, j = (d & 1) * 8 + q;
        float s = 0.0f;
        #pragma unroll
        for (int ww = 0; ww < 8; ww++) s += red[(ww * 32 + ln) * 16 + j];
        out[d * NQ + q0 + q] = s;
    }
}

// ---------------------------------------------------------------------------
extern "C" void kernel_launch(void* const* d_in, const int* in_sizes, int n_in,
                              void* d_out, int out_size)
{
    const float* query = (const float*)d_in[0];
    const float* key   = (const float*)d_in[1];
    const float* value = (const float*)d_in[2];
    const float* W1    = (const float*)d_in[3];
    const float* b1    = (const float*)d_in[4];
    const float* W2    = (const float*)d_in[5];
    const float* b2    = (const float*)d_in[6];

    float* out_p    = (float*)d_out;
    float* scores_p = (float*)d_out + NQ * D;

    k_proj<<<48, 256>>>(query, key, W1, b1);
    k_transpose<<<dim3(NK / 32, D / 32), dim3(32, 8)>>>(value);
    k_scores<<<dim3(NQ / 64, NK / 64), 256>>>(W2, b2, scores_p);
    k_stats<<<NQ, 256>>>(scores_p);
    k_pv<<<NQ / 8, 256>>>(scores_p, out_p);
}

// round 4
// speedup vs baseline: 1.9431x; 1.0373x over previous
#include <cuda_runtime.h>
#include <math_constants.h>

#define NQ 1024
#define NK 2048
#define D  64
typedef unsigned long long ull;

__device__ float g_qp [NQ * D];
__device__ float g_kpb[NK * D];
__device__ float g_vt [NK * D];
__device__ float g_sumexp[NQ];

__device__ __forceinline__ unsigned su32(const void* p) {
    return (unsigned)__cvta_generic_to_shared(p);
}
#define CPA16(dst, src) asm volatile("cp.async.ca.shared.global [%0], [%1], 16;" :: "r"(dst), "l"(src))
#define CPCOMMIT() asm volatile("cp.async.commit_group;")
#define CPWAIT() asm volatile("cp.async.wait_group 0;")
#define FMA2(acc, a, b) asm("fma.rn.f32x2 %0, %1, %2, %0;" : "+l"(acc) : "l"(a), "l"(b))
#define RELU_FMA2(acc, a, b, w) asm("{\n\t.reg .b64 t;\n\t.reg .f32 lo, hi;\n\t" \
    "add.rn.f32x2 t, %1, %2;\n\tmov.b64 {lo, hi}, t;\n\t"                        \
    "max.f32 lo, lo, 0f00000000;\n\tmax.f32 hi, hi, 0f00000000;\n\t"             \
    "mov.b64 t, {lo, hi};\n\tfma.rn.f32x2 %0, %3, t, %0;\n\t}"                   \
    : "+l"(acc) : "l"(a), "l"(b), "l"(w))

// ---- Kernel 1: fused projections + V transpose + sumexp zeroing. ----
// blocks 0..15: qp cols, 16..47: kpb cols, 48..79: transpose (4 32x32 tiles ea)
__global__ void __launch_bounds__(256) k_proj(const float* __restrict__ query,
                                              const float* __restrict__ key,
                                              const float* __restrict__ value,
                                              const float* __restrict__ W1,
                                              const float* __restrict__ b1)
{
    int b = blockIdx.x;
    int tid = threadIdx.x;

    if (b >= 48) {                      // ---- transpose + zero sumexp ----
        __shared__ float tile[32][33];
        int bt = b - 48;                // 0..31
        if (bt < 4) g_sumexp[bt * 256 + tid] = 0.0f;
        int tx = tid & 31, ty5 = tid >> 5;   // ty5: 0..7
        #pragma unroll
        for (int j = 0; j < 4; j++) {
            int t4 = bt * 4 + j;        // 0..127
            int ik = t4 >> 1, id = t4 & 1;
            int kx = ik * 32 + tx, d0 = id * 32;
            __syncthreads();
            #pragma unroll
            for (int r = 0; r < 32; r += 8)
                tile[ty5 + r][tx] = value[(d0 + ty5 + r) * NK + kx];
            __syncthreads();
            int dx = d0 + tx, k0 = ik * 32;
            #pragma unroll
            for (int r = 0; r < 32; r += 8)
                g_vt[(k0 + ty5 + r) * D + dx] = tile[tx][ty5 + r];
        }
        return;
    }

    __shared__ float Ws[D][D];
    __shared__ float Xs[D][64];
    bool isQ = (b < 16);
    int c0 = (isQ ? b : (b - 16)) * 64;
    const float* src = isQ ? query : key;
    int stride = isQ ? NQ : NK;
    int wofs = isQ ? 0 : D;

    {
        int h = tid >> 2, ds = (tid & 3) * 16;
        const float* wr = W1 + h * (2 * D) + wofs + ds;
        #pragma unroll
        for (int j = 0; j < 4; j++) {
            float4 v = *(const float4*)(wr + 4 * j);
            Ws[ds + 4*j + 0][h] = v.x; Ws[ds + 4*j + 1][h] = v.y;
            Ws[ds + 4*j + 2][h] = v.z; Ws[ds + 4*j + 3][h] = v.w;
        }
    }
    {
        int d = tid >> 2, cs = (tid & 3) * 16;
        #pragma unroll
        for (int j = 0; j < 4; j++)
            *(float4*)&Xs[d][cs + 4*j] = *(const float4*)&src[d * stride + c0 + cs + 4*j];
    }
    __syncthreads();

    int h = tid & 63, cg = tid >> 6;
    float acc[16];
    float bias = isQ ? 0.0f : b1[h];
    #pragma unroll
    for (int j = 0; j < 16; j++) acc[j] = bias;

    #pragma unroll 8
    for (int d = 0; d < D; d++) {
        float w = Ws[d][h];
        #pragma unroll
        for (int j = 0; j < 16; j++) acc[j] += w * Xs[d][cg * 16 + j];
    }
    float* dst = isQ ? g_qp : g_kpb;
    #pragma unroll
    for (int j = 0; j < 16; j++)
        dst[(c0 + cg * 16 + j) * D + h] = acc[j];
}

// ---- Kernel 2: scores = W2·relu(qp+kpb)+b2, plus per-row sum(exp(s)). ----
__global__ void __launch_bounds__(256) k_scores(const float* __restrict__ W2,
                                                const float* __restrict__ b2,
                                                float* __restrict__ scores)
{
    __shared__ float qs[64][66];
    __shared__ float ks[64][66];
    __shared__ ull w2s[32];
    int qbase = blockIdx.x * 64, kbase = blockIdx.y * 64;
    int tid = threadIdx.x;

    for (int i = tid; i < 64 * 32; i += 256) {
        int r = i >> 5, c = (i & 31) * 2;
        *(float2*)&qs[r][c] = *(const float2*)&g_qp [(qbase + r) * D + c];
        *(float2*)&ks[r][c] = *(const float2*)&g_kpb[(kbase + r) * D + c];
    }
    if (tid < 32) {
        float2 w = *(const float2*)&W2[2 * tid];
        ull p; asm("mov.b64 %0, {%1,%2};" : "=l"(p) : "f"(w.x), "f"(w.y));
        w2s[tid] = p;
    }
    __syncthreads();

    int tx = tid & 15, ty = tid >> 4;
    ull acc[4][4];
    #pragma unroll
    for (int i = 0; i < 4; i++)
        #pragma unroll
        for (int j = 0; j < 4; j++) acc[i][j] = 0ull;

    #pragma unroll 4
    for (int h = 0; h < 64; h += 2) {
        ull w2 = w2s[h >> 1];
        ull a[4], bb[4];
        #pragma unroll
        for (int i = 0; i < 4; i++) a[i]  = *(ull*)&qs[ty + 16 * i][h];
        #pragma unroll
        for (int j = 0; j < 4; j++) bb[j] = *(ull*)&ks[tx + 16 * j][h];
        #pragma unroll
        for (int i = 0; i < 4; i++)
            #pragma unroll
            for (int j = 0; j < 4; j++)
                RELU_FMA2(acc[i][j], a[i], bb[j], w2);
    }

    float bias = b2[0];
    #pragma unroll
    for (int i = 0; i < 4; i++) {
        int q = qbase + ty + 16 * i;
        float rsum = 0.0f;
        #pragma unroll
        for (int j = 0; j < 4; j++) {
            float lo, hi;
            asm("mov.b64 {%0,%1}, %2;" : "=f"(lo), "=f"(hi) : "l"(acc[i][j]));
            float s = lo + hi + bias;
            scores[q * NK + kbase + tx + 16 * j] = s;
            rsum += __expf(s);
        }
        // reduce over tx (16 contiguous lanes share a q-row)
        #pragma unroll
        for (int o = 8; o > 0; o >>= 1)
            rsum += __shfl_xor_sync(~0u, rsum, o);
        if (tx == 0) atomicAdd(&g_sumexp[q], rsum);
    }
}

// ---- Kernel 3: out[d][q] = sum_k exp(s)/Z * vt[k][d]. 128 blocks x 8q. ----
__global__ void __launch_bounds__(256) k_pv(const float* __restrict__ scores,
                                            float* __restrict__ out)
{
    __shared__ float vs[2][64][68];
    __shared__ float ps[2][64][8];

    int q0 = blockIdx.x * 8;
    int tid = threadIdx.x, w = tid >> 5, lane = tid & 31;

    int sq = tid & 7, skk = tid >> 3;
    float ri = 1.0f / g_sumexp[q0 + sq];
    const float* srow = scores + (q0 + sq) * NK + skk;

    int vk = tid >> 2, vh = (tid & 3) * 16;

    {
        const float* src = g_vt + vk * D + vh;
        unsigned dst = su32(&vs[0][vk][vh]);
        #pragma unroll
        for (int j = 0; j < 4; j++) CPA16(dst + 16 * j, src + 4 * j);
        CPCOMMIT();
    }
    float sc0 = srow[0], sc1 = srow[32];

    ull accx[4] = {0,0,0,0};
    ull accy[4] = {0,0,0,0};

    for (int t = 0; t < 32; t++) {
        int buf = t & 1;
        CPWAIT();
        __syncthreads();
        ps[buf][skk     ][sq] = __expf(sc0) * ri;
        ps[buf][skk + 32][sq] = __expf(sc1) * ri;
        if (t < 31) {
            const float* src = g_vt + ((t + 1) * 64 + vk) * D + vh;
            unsigned dst = su32(&vs[buf ^ 1][vk][vh]);
            #pragma unroll
            for (int j = 0; j < 4; j++) CPA16(dst + 16 * j, src + 4 * j);
            CPCOMMIT();
            sc0 = srow[(t + 1) * 64];
            sc1 = srow[(t + 1) * 64 + 32];
        }
        __syncthreads();

        int kb = w * 8;
        #pragma unroll
        for (int u = 0; u < 8; u++) {
            int kk = kb + u;
            float2 v = *(float2*)&vs[buf][kk][2 * lane];
            ulonglong2 pA = *(ulonglong2*)&ps[buf][kk][0];
            ulonglong2 pB = *(ulonglong2*)&ps[buf][kk][4];
            ull vx, vy;
            asm("mov.b64 %0, {%1,%1};" : "=l"(vx) : "f"(v.x));
            asm("mov.b64 %0, {%1,%1};" : "=l"(vy) : "f"(v.y));
            FMA2(accx[0], pA.x, vx); FMA2(accx[1], pA.y, vx);
            FMA2(accx[2], pB.x, vx); FMA2(accx[3], pB.y, vx);
            FMA2(accy[0], pA.x, vy); FMA2(accy[1], pA.y, vy);
            FMA2(accy[2], pB.x, vy); FMA2(accy[3], pB.y, vy);
        }
    }

    __syncthreads();
    float* red = (float*)vs;
    int base = (w * 32 + lane) * 16;
    #pragma unroll
    for (int jp = 0; jp < 4; jp++) {
        float lo, hi;
        asm("mov.b64 {%0,%1}, %2;" : "=f"(lo), "=f"(hi) : "l"(accx[jp]));
        red[base + 2 * jp] = lo; red[base + 2 * jp + 1] = hi;
        asm("mov.b64 {%0,%1}, %2;" : "=f"(lo), "=f"(hi) : "l"(accy[jp]));
        red[base + 8 + 2 * jp] = lo; red[base + 8 + 2 * jp + 1] = hi;
    }
    __syncthreads();

    #pragma unroll
    for (int r = tid; r < 512; r += 256) {
        int d = r >> 3, q = r & 7;
        int ln = d >> 1, j = (d & 1) * 8 + q;
        float s = 0.0f;
        #pragma unroll
        for (int ww = 0; ww < 8; ww++) s += red[(ww * 32 + ln) * 16 + j];
        out[d * NQ + q0 + q] = s;
    }
}

// ---------------------------------------------------------------------------
extern "C" void kernel_launch(void* const* d_in, const int* in_sizes, int n_in,
                              void* d_out, int out_size)
{
    const float* query = (const float*)d_in[0];
    const float* key   = (const float*)d_in[1];
    const float* value = (const float*)d_in[2];
    const float* W1    = (const float*)d_in[3];
    const float* b1    = (const float*)d_in[4];
    const float* W2    = (const float*)d_in[5];
    const float* b2    = (const float*)d_in[6];

    float* out_p    = (float*)d_out;
    float* scores_p = (float*)d_out + NQ * D;

    k_proj<<<80, 256>>>(query, key, value, W1, b1);
    k_scores<<<dim3(NQ / 64, NK / 64), 256>>>(W2, b2, scores_p);
    k_pv<<<NQ / 8, 256>>>(scores_p, out_p);
}

// round 5
// speedup vs baseline: 2.2058x; 1.1352x over previous
#include <cuda_runtime.h>
#include <math_constants.h>

#define NQ 1024
#define NK 2048
#define D  64
typedef unsigned long long ull;

__device__ float g_qp [NQ * D];
__device__ float g_kpb[NK * D];
__device__ float g_vt [NK * D];
__device__ float g_sumexp[NQ];

__device__ __forceinline__ unsigned su32(const void* p) {
    return (unsigned)__cvta_generic_to_shared(p);
}
#define CPA16(dst, src) asm volatile("cp.async.ca.shared.global [%0], [%1], 16;" :: "r"(dst), "l"(src))
#define CPCOMMIT() asm volatile("cp.async.commit_group;")
#define CPWAIT() asm volatile("cp.async.wait_group 0;")
#define FMA2(acc, a, b) asm("fma.rn.f32x2 %0, %1, %2, %0;" : "+l"(acc) : "l"(a), "l"(b))
#define RELU_FMA2(acc, a, b, w) asm("{\n\t.reg .b64 t;\n\t.reg .f32 lo, hi;\n\t" \
    "add.rn.f32x2 t, %1, %2;\n\tmov.b64 {lo, hi}, t;\n\t"                        \
    "max.f32 lo, lo, 0f00000000;\n\tmax.f32 hi, hi, 0f00000000;\n\t"             \
    "mov.b64 t, {lo, hi};\n\tfma.rn.f32x2 %0, %3, t, %0;\n\t}"                   \
    : "+l"(acc) : "l"(a), "l"(b), "l"(w))

// ---- Kernel 1: fused projections + V transpose + zeroing. 224 blocks. ----
// blocks 0..31: qp (32 cols), 32..95: kpb (32 cols), 96..223: one 32x32 tile.
__global__ void __launch_bounds__(256) k_proj(const float* __restrict__ query,
                                              const float* __restrict__ key,
                                              const float* __restrict__ value,
                                              const float* __restrict__ W1,
                                              const float* __restrict__ b1,
                                              float* __restrict__ out)
{
    int b = blockIdx.x;
    int tid = threadIdx.x;

    if (b >= 96) {                      // ---- transpose tile + zeroing ----
        __shared__ float tile[32][33];
        int bt = b - 96;                // 0..127
        if (bt < 4) g_sumexp[bt * 256 + tid] = 0.0f;
        if (bt < 64) *(float4*)&out[bt * 1024 + tid * 4] = make_float4(0.f, 0.f, 0.f, 0.f);
        int ik = bt >> 1, id = bt & 1;
        int k0 = ik * 32, d0 = id * 32;
        int tx = tid & 31, ty = tid >> 5;   // ty 0..7
        #pragma unroll
        for (int r = 0; r < 32; r += 8)
            tile[ty + r][tx] = value[(d0 + ty + r) * NK + k0 + tx];
        __syncthreads();
        #pragma unroll
        for (int r = 0; r < 32; r += 8)
            g_vt[(k0 + ty + r) * D + d0 + tx] = tile[tx][ty + r];
        return;
    }

    __shared__ float Ws[D][D];          // Ws[d][h]
    __shared__ float Xs[D][32];
    bool isQ = (b < 32);
    int c0 = (isQ ? b : (b - 32)) * 32;
    const float* src = isQ ? query : key;
    int stride = isQ ? NQ : NK;
    int wofs = isQ ? 0 : D;

    {   // W half: 4096 floats = 16/thread
        int h = tid >> 2, ds = (tid & 3) * 16;
        const float* wr = W1 + h * (2 * D) + wofs + ds;
        #pragma unroll
        for (int j = 0; j < 4; j++) {
            float4 v = *(const float4*)(wr + 4 * j);
            Ws[ds + 4*j + 0][h] = v.x; Ws[ds + 4*j + 1][h] = v.y;
            Ws[ds + 4*j + 2][h] = v.z; Ws[ds + 4*j + 3][h] = v.w;
        }
    }
    {   // X tile 64x32: 512 float4, 2/thread
        #pragma unroll
        for (int j = 0; j < 2; j++) {
            int f = tid * 2 + j;
            int d = f >> 3, c = (f & 7) * 4;
            *(float4*)&Xs[d][c] = *(const float4*)&src[d * stride + c0 + c];
        }
    }
    __syncthreads();

    int h = tid & 63, cg = tid >> 6;    // 8 cols per thread
    float acc[8];
    float bias = isQ ? 0.0f : b1[h];
    #pragma unroll
    for (int j = 0; j < 8; j++) acc[j] = bias;

    #pragma unroll 16
    for (int d = 0; d < D; d++) {
        float w = Ws[d][h];
        #pragma unroll
        for (int j = 0; j < 8; j++) acc[j] += w * Xs[d][cg * 8 + j];
    }
    float* dst = isQ ? g_qp : g_kpb;
    #pragma unroll
    for (int j = 0; j < 8; j++)
        dst[(c0 + cg * 8 + j) * D + h] = acc[j];
}

// ---- Kernel 2: scores = W2·relu(qp+kpb)+b2, plus per-row sum(exp(s)). ----
__global__ void __launch_bounds__(256) k_scores(const float* __restrict__ W2,
                                                const float* __restrict__ b2,
                                                float* __restrict__ scores)
{
    __shared__ float qs[64][66];
    __shared__ float ks[64][66];
    __shared__ ull w2s[32];
    int qbase = blockIdx.x * 64, kbase = blockIdx.y * 64;
    int tid = threadIdx.x;

    for (int i = tid; i < 64 * 32; i += 256) {
        int r = i >> 5, c = (i & 31) * 2;
        *(float2*)&qs[r][c] = *(const float2*)&g_qp [(qbase + r) * D + c];
        *(float2*)&ks[r][c] = *(const float2*)&g_kpb[(kbase + r) * D + c];
    }
    if (tid < 32) {
        float2 w = *(const float2*)&W2[2 * tid];
        ull p; asm("mov.b64 %0, {%1,%2};" : "=l"(p) : "f"(w.x), "f"(w.y));
        w2s[tid] = p;
    }
    __syncthreads();

    int tx = tid & 15, ty = tid >> 4;
    ull acc[4][4];
    #pragma unroll
    for (int i = 0; i < 4; i++)
        #pragma unroll
        for (int j = 0; j < 4; j++) acc[i][j] = 0ull;

    #pragma unroll 4
    for (int h = 0; h < 64; h += 2) {
        ull w2 = w2s[h >> 1];
        ull a[4], bb[4];
        #pragma unroll
        for (int i = 0; i < 4; i++) a[i]  = *(ull*)&qs[ty + 16 * i][h];
        #pragma unroll
        for (int j = 0; j < 4; j++) bb[j] = *(ull*)&ks[tx + 16 * j][h];
        #pragma unroll
        for (int i = 0; i < 4; i++)
            #pragma unroll
            for (int j = 0; j < 4; j++)
                RELU_FMA2(acc[i][j], a[i], bb[j], w2);
    }

    float bias = b2[0];
    #pragma unroll
    for (int i = 0; i < 4; i++) {
        int q = qbase + ty + 16 * i;
        float rsum = 0.0f;
        #pragma unroll
        for (int j = 0; j < 4; j++) {
            float lo, hi;
            asm("mov.b64 {%0,%1}, %2;" : "=f"(lo), "=f"(hi) : "l"(acc[i][j]));
            float s = lo + hi + bias;
            scores[q * NK + kbase + tx + 16 * j] = s;
            rsum += __expf(s);
        }
        #pragma unroll
        for (int o = 8; o > 0; o >>= 1)
            rsum += __shfl_xor_sync(~0u, rsum, o);
        if (tx == 0) atomicAdd(&g_sumexp[q], rsum);
    }
}

// ---- Kernel 3: out[d][q] += sum_k exp(s)/Z * vt[k][d]. k-split 2. ----
// 256 blocks: q0 = (b>>1)*8, k-half = b&1 (1024 k each).
__global__ void __launch_bounds__(256) k_pv(const float* __restrict__ scores,
                                            float* __restrict__ out)
{
    __shared__ float vs[2][64][68];
    __shared__ float ps[2][64][8];

    int q0 = (blockIdx.x >> 1) * 8;
    int kb0 = (blockIdx.x & 1) * (NK / 2);
    int tid = threadIdx.x, w = tid >> 5, lane = tid & 31;

    int sq = tid & 7, skk = tid >> 3;
    float ri = 1.0f / g_sumexp[q0 + sq];
    const float* srow = scores + (q0 + sq) * NK + kb0 + skk;

    int vk = tid >> 2, vh = (tid & 3) * 16;

    {
        const float* src = g_vt + (kb0 + vk) * D + vh;
        unsigned dst = su32(&vs[0][vk][vh]);
        #pragma unroll
        for (int j = 0; j < 4; j++) CPA16(dst + 16 * j, src + 4 * j);
        CPCOMMIT();
    }
    float sc0 = srow[0], sc1 = srow[32];

    ull accx[4] = {0,0,0,0};
    ull accy[4] = {0,0,0,0};

    for (int t = 0; t < 16; t++) {
        int buf = t & 1;
        CPWAIT();
        __syncthreads();
        ps[buf][skk     ][sq] = __expf(sc0) * ri;
        ps[buf][skk + 32][sq] = __expf(sc1) * ri;
        if (t < 15) {
            const float* src = g_vt + (kb0 + (t + 1) * 64 + vk) * D + vh;
            unsigned dst = su32(&vs[buf ^ 1][vk][vh]);
            #pragma unroll
            for (int j = 0; j < 4; j++) CPA16(dst + 16 * j, src + 4 * j);
            CPCOMMIT();
            sc0 = srow[(t + 1) * 64];
            sc1 = srow[(t + 1) * 64 + 32];
        }
        __syncthreads();

        int kb = w * 8;
        #pragma unroll
        for (int u = 0; u < 8; u++) {
            int kk = kb + u;
            float2 v = *(float2*)&vs[buf][kk][2 * lane];
            ulonglong2 pA = *(ulonglong2*)&ps[buf][kk][0];
            ulonglong2 pB = *(ulonglong2*)&ps[buf][kk][4];
            ull vx, vy;
            asm("mov.b64 %0, {%1,%1};" : "=l"(vx) : "f"(v.x));
            asm("mov.b64 %0, {%1,%1};" : "=l"(vy) : "f"(v.y));
            FMA2(accx[0], pA.x, vx); FMA2(accx[1], pA.y, vx);
            FMA2(accx[2], pB.x, vx); FMA2(accx[3], pB.y, vx);
            FMA2(accy[0], pA.x, vy); FMA2(accy[1], pA.y, vy);
            FMA2(accy[2], pB.x, vy); FMA2(accy[3], pB.y, vy);
        }
    }

    __syncthreads();
    float* red = (float*)vs;
    int base = (w * 32 + lane) * 16;
    #pragma unroll
    for (int jp = 0; jp < 4; jp++) {
        float lo, hi;
        asm("mov.b64 {%0,%1}, %2;" : "=f"(lo), "=f"(hi) : "l"(accx[jp]));
        red[base + 2 * jp] = lo; red[base + 2 * jp + 1] = hi;
        asm("mov.b64 {%0,%1}, %2;" : "=f"(lo), "=f"(hi) : "l"(accy[jp]));
        red[base + 8 + 2 * jp] = lo; red[base + 8 + 2 * jp + 1] = hi;
    }
    __syncthreads();

    #pragma unroll
    for (int r = tid; r < 512; r += 256) {
        int d = r >> 3, q = r & 7;
        int ln = d >> 1, j = (d & 1) * 8 + q;
        float s = 0.0f;
        #pragma unroll
        for (int ww = 0; ww < 8; ww++) s += red[(ww * 32 + ln) * 16 + j];
        atomicAdd(&out[d * NQ + q0 + q], s);
    }
}

// ---------------------------------------------------------------------------
extern "C" void kernel_launch(void* const* d_in, const int* in_sizes, int n_in,
                              void* d_out, int out_size)
{
    const float* query = (const float*)d_in[0];
    const float* key   = (const float*)d_in[1];
    const float* value = (const float*)d_in[2];
    const float* W1    = (const float*)d_in[3];
    const float* b1    = (const float*)d_in[4];
    const float* W2    = (const float*)d_in[5];
    const float* b2    = (const float*)d_in[6];

    float* out_p    = (float*)d_out;
    float* scores_p = (float*)d_out + NQ * D;

    k_proj<<<224, 256>>>(query, key, value, W1, b1, out_p);
    k_scores<<<dim3(NQ / 64, NK / 64), 256>>>(W2, b2, scores_p);
    k_pv<<<256, 256>>>(scores_p, out_p);
}